// round 10
// baseline (speedup 1.0000x reference)
#include <cuda_runtime.h>
#include <cuda_fp16.h>
#include <cstdint>

#define MN  50000
#define MNP 50176          // padded to 392*128 (unconditional GEMM tile loads)
#define NE  800000

// ---------------- scratch (device globals; no allocs allowed) ---------------
__device__ __half g_agg[(size_t)MNP * 256];     // aggregation out (GEMM A input)
__device__ __half g_h[(size_t)MNP * 256];       // MLP hidden
__device__ __half g_act[(size_t)MNP * 256];     // layer output (next agg input)
__device__ __half g_wHi[6][65536];              // weight hi (transposed [N,K])
__device__ __half g_wLo[6][65536];              // weight lo
__device__ int g_row[MN + 1];
__device__ int g_cnt[MN];
__device__ int g_srcs[NE];

// ---------------- helpers ---------------------------------------------------
__device__ __forceinline__ uint32_t smem_u32(const void* p) {
    return (uint32_t)__cvta_generic_to_shared((void*)p);
}
__device__ __forceinline__ void cp_async16(uint32_t dst, const void* src) {
    asm volatile("cp.async.cg.shared.global [%0], [%1], 16;" :: "r"(dst), "l"(src));
}
__device__ __forceinline__ void cp_commit() {
    asm volatile("cp.async.commit_group;" ::: "memory");
}
template <int n>
__device__ __forceinline__ void cp_wait() {
    asm volatile("cp.async.wait_group %0;" :: "n"(n) : "memory");
}
__device__ __forceinline__ void ldsm_x4(uint32_t& r0, uint32_t& r1, uint32_t& r2,
                                        uint32_t& r3, uint32_t addr) {
    asm volatile("ldmatrix.sync.aligned.m8n8.x4.shared.b16 {%0,%1,%2,%3}, [%4];"
                 : "=r"(r0), "=r"(r1), "=r"(r2), "=r"(r3) : "r"(addr));
}

// ---------------- CSR build -------------------------------------------------
__global__ void k_zero_cnt() {
    int i = blockIdx.x * blockDim.x + threadIdx.x;
    if (i < MN) g_cnt[i] = 0;
}
__global__ void k_count(const int* __restrict__ ei) {
    int e = blockIdx.x * blockDim.x + threadIdx.x;
    if (e < NE) {
        int dst = ei[NE + e];
        if (dst >= 0 && dst < MN) atomicAdd(&g_cnt[dst], 1);
    }
}
__global__ void k_scan() {
    __shared__ int ssum[1024];
    const int t = threadIdx.x;
    const int CH = (MN + 1023) / 1024;
    const int base = t * CH;
    int s = 0;
    for (int i = 0; i < CH; i++) { int idx = base + i; if (idx < MN) s += g_cnt[idx]; }
    ssum[t] = s;
    __syncthreads();
    for (int off = 1; off < 1024; off <<= 1) {
        int v = (t >= off) ? ssum[t - off] : 0;
        __syncthreads();
        ssum[t] += v;
        __syncthreads();
    }
    int run = ssum[t] - s;
    for (int i = 0; i < CH; i++) {
        int idx = base + i;
        if (idx < MN) { int c = g_cnt[idx]; g_row[idx] = run; run += c; g_cnt[idx] = 0; }
    }
    if (t == 1023) g_row[MN] = ssum[1023];
}
__global__ void k_fill(const int* __restrict__ ei) {
    int e = blockIdx.x * blockDim.x + threadIdx.x;
    if (e < NE) {
        int src = ei[e];
        int dst = ei[NE + e];
        if (src >= 0 && src < MN && dst >= 0 && dst < MN) {
            int pos = atomicAdd(&g_cnt[dst], 1);
            g_srcs[g_row[dst] + pos] = src;
        }
    }
}

// ---------------- weight convert: W[K,N] fp32 -> hi/lo fp16 [N,K] -----------
__global__ void k_wcvt(const float* __restrict__ W, __half* __restrict__ hi,
                       __half* __restrict__ lo, int K, int N) {
    __shared__ float t[32][33];
    const int kb = blockIdx.y * 32, nb = blockIdx.x * 32;
    const int tx = threadIdx.x, ty0 = threadIdx.y;
#pragma unroll
    for (int i = 0; i < 4; i++) {
        int ty = ty0 + 8 * i;
        t[ty][tx] = W[(size_t)(kb + ty) * N + nb + tx];
    }
    __syncthreads();
#pragma unroll
    for (int i = 0; i < 4; i++) {
        int n = ty0 + 8 * i;
        float v = t[tx][n];
        __half h = __float2half_rn(v);
        hi[(size_t)(nb + n) * K + kb + tx] = h;
        lo[(size_t)(nb + n) * K + kb + tx] = __float2half_rn(v - __half2float(h));
    }
}

// ---------------- aggregation: (fp32|fp16 in) -> fp16 out, fp32 accum -------
__device__ __forceinline__ float4 load4(const float* p) {
    return *(const float4*)p;
}
__device__ __forceinline__ float4 load4(const __half* p) {
    uint2 u = __ldg((const uint2*)p);
    float2 a = __half22float2(*(__half2*)&u.x);
    float2 b = __half22float2(*(__half2*)&u.y);
    return make_float4(a.x, a.y, b.x, b.y);
}

template <int VEC, typename T>
__global__ void k_agg(const T* __restrict__ x, __half* __restrict__ oh) {
    const int node = (blockIdx.x * blockDim.x + threadIdx.x) >> 5;
    if (node >= MN) return;
    const int lane = threadIdx.x & 31;
    const int F = VEC * 128;

    float4 acc0[VEC], acc1[VEC];
#pragma unroll
    for (int v = 0; v < VEC; v++) {
        acc0[v] = load4(x + (size_t)node * F + (lane + 32 * v) * 4);
        acc1[v] = make_float4(0.f, 0.f, 0.f, 0.f);
    }

    const int s = g_row[node];
    const int e = g_row[node + 1];
    for (int i = s; i < e; i += 32) {
        const int my = (i + lane < e) ? g_srcs[i + lane] : 0;
        const int cnt = min(32, e - i);
        int t = 0;
        for (; t + 2 <= cnt; t += 2) {
            const int s0 = __shfl_sync(0xffffffff, my, t);
            const int s1 = __shfl_sync(0xffffffff, my, t + 1);
            const T* p0 = x + (size_t)s0 * F;
            const T* p1 = x + (size_t)s1 * F;
#pragma unroll
            for (int v = 0; v < VEC; v++) {
                float4 q0 = load4(p0 + (lane + 32 * v) * 4);
                float4 q1 = load4(p1 + (lane + 32 * v) * 4);
                acc0[v].x += q0.x; acc0[v].y += q0.y; acc0[v].z += q0.z; acc0[v].w += q0.w;
                acc1[v].x += q1.x; acc1[v].y += q1.y; acc1[v].z += q1.z; acc1[v].w += q1.w;
            }
        }
        if (t < cnt) {
            const int s0 = __shfl_sync(0xffffffff, my, t);
            const T* p0 = x + (size_t)s0 * F;
#pragma unroll
            for (int v = 0; v < VEC; v++) {
                float4 q0 = load4(p0 + (lane + 32 * v) * 4);
                acc0[v].x += q0.x; acc0[v].y += q0.y; acc0[v].z += q0.z; acc0[v].w += q0.w;
            }
        }
    }
#pragma unroll
    for (int v = 0; v < VEC; v++) {
        __half2 p0 = __floats2half2_rn(acc0[v].x + acc1[v].x, acc0[v].y + acc1[v].y);
        __half2 p1 = __floats2half2_rn(acc0[v].z + acc1[v].z, acc0[v].w + acc1[v].w);
        size_t off = (size_t)node * F + (lane + 32 * v) * 4;
        *(uint2*)(oh + off) = make_uint2(*(uint32_t*)&p0, *(uint32_t*)&p1);
    }
}

// ---------------- mma.sync fp16 GEMM, 3-stage cp.async, 1 barrier/iter ------
// C[M,N] = act(A[M,K] @ (Whi+Wlo) + bias)
// EPI: 0 = fp16 + ReLU, 1 = fp32 (no ReLU, final output)
#define PITCH 40                   // fp16 elems per smem row (80B, conflict-free)
#define TILE_B 10240               // one 128x32 fp16 array, 80B rows
#define BUF_B  (3 * TILE_B)        // A, Bh, Bl
#define NSTAGE 3
#define SM_TOTAL (NSTAGE * BUF_B + 512)

__device__ __forceinline__ void mma16816(float* d, const uint32_t* a, const uint32_t* b) {
    asm volatile("mma.sync.aligned.m16n8k16.row.col.f32.f16.f16.f32 "
                 "{%0,%1,%2,%3}, {%4,%5,%6,%7}, {%8,%9}, {%0,%1,%2,%3};"
                 : "+f"(d[0]), "+f"(d[1]), "+f"(d[2]), "+f"(d[3])
                 : "r"(a[0]), "r"(a[1]), "r"(a[2]), "r"(a[3]), "r"(b[0]), "r"(b[1]));
}

__device__ __forceinline__ void load_tile(
    char* smbase, const __half* __restrict__ A, const __half* __restrict__ Bhi,
    const __half* __restrict__ Blo, int tid, int m0, int n0, int K, int kb) {
    const uint32_t s0 = smem_u32(smbase);
#pragma unroll
    for (int i = 0; i < 2; i++) {
        const int idx = tid + 256 * i;
        const int r = idx >> 2, c4 = idx & 3;
        const uint32_t so = (uint32_t)(r * 80 + c4 * 16);
        const size_t aoff = (size_t)(m0 + r) * K + kb + c4 * 8;
        const size_t boff = (size_t)(n0 + r) * K + kb + c4 * 8;
        cp_async16(s0 + so,              A   + aoff);
        cp_async16(s0 + TILE_B + so,     Bhi + boff);
        cp_async16(s0 + 2 * TILE_B + so, Blo + boff);
    }
}

template <int EPI>
__global__ __launch_bounds__(256, 2)
void k_mmagemm(const __half* __restrict__ A, const __half* __restrict__ Bhi,
               const __half* __restrict__ Blo, const float* __restrict__ bias,
               float* __restrict__ outF, __half* __restrict__ outH,
               int M, int K, int N) {
    extern __shared__ char sm[];
    float* sbias = (float*)(sm + NSTAGE * BUF_B);

    const int tid = threadIdx.x, warp = tid >> 5, lane = tid & 31;
    const int g = lane >> 2, tig = lane & 3;
    const int wm = warp >> 1, wn = warp & 1;      // 4x2 warp grid, 32x64 warp tile
    const int m0 = blockIdx.x * 128, n0 = blockIdx.y * 128;

    if (tid < 128) sbias[tid] = bias[n0 + tid];

    const int aRow = wm * 32 + (lane & 15);
    const int aCol = (lane & 16) ? 8 : 0;
    const uint32_t aOffB = (uint32_t)(aRow * PITCH + aCol) * 2;
    const int bRow = wn * 64 + (lane & 7) + ((lane & 16) ? 8 : 0);
    const int bCol = (lane & 8) ? 8 : 0;
    const uint32_t bOffB = (uint32_t)(bRow * PITCH + bCol) * 2;

    float acc[2][8][4];
#pragma unroll
    for (int i = 0; i < 2; i++)
#pragma unroll
        for (int j = 0; j < 8; j++)
#pragma unroll
            for (int r = 0; r < 4; r++) acc[i][j][r] = 0.f;

    const int NKT = K >> 5;
    // prologue: stages 0 and 1 in flight
    load_tile(sm, A, Bhi, Blo, tid, m0, n0, K, 0);
    cp_commit();
    if (NKT > 1) {
        load_tile(sm + BUF_B, A, Bhi, Blo, tid, m0, n0, K, 32);
        cp_commit();
    }
    const uint32_t smu = smem_u32(sm);

    for (int kt = 0; kt < NKT; kt++) {
        const bool more = (kt + 2 < NKT);
        if (more) cp_wait<1>(); else cp_wait<0>();
        __syncthreads();   // stage kt visible to all; all warps done with stage kt-1
        if (more) {
            load_tile(sm + ((kt + 2) % NSTAGE) * BUF_B, A, Bhi, Blo, tid, m0, n0, K,
                      (kt + 2) * 32);
            cp_commit();
        }

        const uint32_t sAU  = smu + (kt % NSTAGE) * BUF_B;
        const uint32_t sBhU = sAU + TILE_B;
        const uint32_t sBlU = sAU + 2 * TILE_B;

#pragma unroll
        for (int k16 = 0; k16 < 2; k16++) {
            const uint32_t kByte = (uint32_t)(k16 * 16 * 2);
            uint32_t a[2][4];
#pragma unroll
            for (int i = 0; i < 2; i++)
                ldsm_x4(a[i][0], a[i][1], a[i][2], a[i][3],
                        sAU + aOffB + kByte + (uint32_t)(i * 16 * PITCH * 2));
#pragma unroll
            for (int pass = 0; pass < 2; pass++) {
                const uint32_t bBase = ((pass == 0) ? sBhU : sBlU) + bOffB + kByte;
                uint32_t b2[8][2];
#pragma unroll
                for (int jj = 0; jj < 4; jj++)
                    ldsm_x4(b2[2 * jj][0], b2[2 * jj][1], b2[2 * jj + 1][0], b2[2 * jj + 1][1],
                            bBase + (uint32_t)(jj * 16 * PITCH * 2));
#pragma unroll
                for (int i = 0; i < 2; i++)
#pragma unroll
                    for (int j = 0; j < 8; j++) mma16816(acc[i][j], a[i], b2[j]);
            }
        }
    }

    // epilogue
#pragma unroll
    for (int i = 0; i < 2; i++) {
        const int r0 = m0 + wm * 32 + i * 16 + g;
#pragma unroll
        for (int half = 0; half < 2; half++) {
            const int row = r0 + half * 8;
            if (row >= M) continue;
#pragma unroll
            for (int j = 0; j < 8; j++) {
                const int cl = wn * 64 + j * 8 + tig * 2;
                float v0 = acc[i][j][2 * half + 0] + sbias[cl];
                float v1 = acc[i][j][2 * half + 1] + sbias[cl + 1];
                const size_t o = (size_t)row * N + n0 + cl;
                if (EPI == 0) {
                    v0 = fmaxf(v0, 0.f);
                    v1 = fmaxf(v1, 0.f);
                    __half2 hp = __floats2half2_rn(v0, v1);
                    *(uint32_t*)(outH + o) = *(uint32_t*)&hp;
                } else {
                    *(float2*)(outF + o) = make_float2(v0, v1);
                }
            }
        }
    }
}

// ---------------- launch ----------------------------------------------------
static inline void launch_gemm(int epi, const __half* A, const __half* Bhi, const __half* Blo,
                               const float* bias, float* outF, __half* outH,
                               int M, int K, int N) {
    dim3 grid((M + 127) / 128, N / 128);
    if (epi == 0) k_mmagemm<0><<<grid, 256, SM_TOTAL>>>(A, Bhi, Blo, bias, outF, outH, M, K, N);
    else          k_mmagemm<1><<<grid, 256, SM_TOTAL>>>(A, Bhi, Blo, bias, outF, outH, M, K, N);
}

extern "C" void kernel_launch(void* const* d_in, const int* in_sizes, int n_in,
                              void* d_out, int out_size) {
    const float* x  = (const float*)d_in[0];
    const int*   ei = (const int*)d_in[1];   // int32 (JAX x64 disabled)
    const float* W[6]  = {(const float*)d_in[2], (const float*)d_in[4], (const float*)d_in[6],
                          (const float*)d_in[8], (const float*)d_in[10], (const float*)d_in[12]};
    const float* Bv[6] = {(const float*)d_in[3], (const float*)d_in[5], (const float*)d_in[7],
                          (const float*)d_in[9], (const float*)d_in[11], (const float*)d_in[13]};
    const int WK[6] = {128, 128, 256, 256, 128, 128};
    const int WN[6] = {128, 256, 256, 128, 128, 128};
    float* out = (float*)d_out;

    __half *agg, *h, *act, *wHi, *wLo;
    cudaGetSymbolAddress((void**)&agg, g_agg);
    cudaGetSymbolAddress((void**)&h, g_h);
    cudaGetSymbolAddress((void**)&act, g_act);
    cudaGetSymbolAddress((void**)&wHi, g_wHi);
    cudaGetSymbolAddress((void**)&wLo, g_wLo);

    cudaFuncSetAttribute(k_mmagemm<0>, cudaFuncAttributeMaxDynamicSharedMemorySize, SM_TOTAL);
    cudaFuncSetAttribute(k_mmagemm<1>, cudaFuncAttributeMaxDynamicSharedMemorySize, SM_TOTAL);

    // --- CSR build ---
    k_zero_cnt<<<(MN + 255) / 256, 256>>>();
    k_count<<<(NE + 255) / 256, 256>>>(ei);
    k_scan<<<1, 1024>>>();
    k_fill<<<(NE + 255) / 256, 256>>>(ei);

    // --- weight conversion (tiled transpose + fp16 hi/lo split) ---
    for (int i = 0; i < 6; i++) {
        dim3 g(WN[i] / 32, WK[i] / 32), blk(32, 8);
        k_wcvt<<<g, blk>>>(W[i], wHi + (size_t)i * 65536, wLo + (size_t)i * 65536, WK[i], WN[i]);
    }

    const int AGG_BLOCKS = (MN * 32 + 255) / 256;

    // --- layer 1 (agg reads fp32 harness input) ---
    k_agg<1, float><<<AGG_BLOCKS, 256>>>(x, agg);
    launch_gemm(0, agg, wHi + 0 * 65536, wLo + 0 * 65536, Bv[0], nullptr, h, MN, 128, 128);
    launch_gemm(0, h,   wHi + 1 * 65536, wLo + 1 * 65536, Bv[1], nullptr, act, MN, 128, 256);

    // --- layer 2 (fp16 gather) ---
    k_agg<2, __half><<<AGG_BLOCKS, 256>>>(act, agg);
    launch_gemm(0, agg, wHi + 2 * 65536, wLo + 2 * 65536, Bv[2], nullptr, h, MN, 256, 256);
    launch_gemm(0, h,   wHi + 3 * 65536, wLo + 3 * 65536, Bv[3], nullptr, act, MN, 256, 128);

    // --- layer 3 (fp16 gather) ---
    k_agg<1, __half><<<AGG_BLOCKS, 256>>>(act, agg);
    launch_gemm(0, agg, wHi + 4 * 65536, wLo + 4 * 65536, Bv[4], nullptr, h, MN, 128, 128);
    launch_gemm(1, h,   wHi + 5 * 65536, wLo + 5 * 65536, Bv[5], out, nullptr, MN, 128, 128);
}

// round 11
// speedup vs baseline: 1.0393x; 1.0393x over previous
#include <cuda_runtime.h>
#include <cuda_fp16.h>
#include <cstdint>

#define MN  50000
#define MNP 50176          // padded to 392*128 (unconditional GEMM tile loads)
#define NE  800000

// ---------------- scratch (device globals; no allocs allowed) ---------------
__device__ __half g_agg[(size_t)MNP * 256];     // aggregation out (layer A input)
__device__ __half g_act[(size_t)MNP * 256];     // layer output (next agg input)
__device__ __half g_wHi[6][65536];              // weight hi (transposed [N,K])
__device__ __half g_wLo[6][65536];              // weight lo
__device__ int g_row[MN + 1];
__device__ int g_cnt[MN];
__device__ int g_srcs[NE];

// ---------------- helpers ---------------------------------------------------
__device__ __forceinline__ uint32_t smem_u32(const void* p) {
    return (uint32_t)__cvta_generic_to_shared((void*)p);
}
__device__ __forceinline__ void cp_async16(uint32_t dst, const void* src) {
    asm volatile("cp.async.cg.shared.global [%0], [%1], 16;" :: "r"(dst), "l"(src));
}
__device__ __forceinline__ void cp_commit() {
    asm volatile("cp.async.commit_group;" ::: "memory");
}
template <int n>
__device__ __forceinline__ void cp_wait() {
    asm volatile("cp.async.wait_group %0;" :: "n"(n) : "memory");
}
__device__ __forceinline__ void ldsm_x4(uint32_t& r0, uint32_t& r1, uint32_t& r2,
                                        uint32_t& r3, uint32_t addr) {
    asm volatile("ldmatrix.sync.aligned.m8n8.x4.shared.b16 {%0,%1,%2,%3}, [%4];"
                 : "=r"(r0), "=r"(r1), "=r"(r2), "=r"(r3) : "r"(addr));
}
__device__ __forceinline__ void mma16816(float* d, const uint32_t* a, const uint32_t* b) {
    asm volatile("mma.sync.aligned.m16n8k16.row.col.f32.f16.f16.f32 "
                 "{%0,%1,%2,%3}, {%4,%5,%6,%7}, {%8,%9}, {%0,%1,%2,%3};"
                 : "+f"(d[0]), "+f"(d[1]), "+f"(d[2]), "+f"(d[3])
                 : "r"(a[0]), "r"(a[1]), "r"(a[2]), "r"(a[3]), "r"(b[0]), "r"(b[1]));
}

// ---------------- CSR build -------------------------------------------------
__global__ void k_zero_cnt() {
    int i = blockIdx.x * blockDim.x + threadIdx.x;
    if (i < MN) g_cnt[i] = 0;
}
__global__ void k_count(const int* __restrict__ ei) {
    int e = blockIdx.x * blockDim.x + threadIdx.x;
    if (e < NE) {
        int dst = ei[NE + e];
        if (dst >= 0 && dst < MN) atomicAdd(&g_cnt[dst], 1);
    }
}
__global__ void k_scan() {
    __shared__ int ssum[1024];
    const int t = threadIdx.x;
    const int CH = (MN + 1023) / 1024;
    const int base = t * CH;
    int s = 0;
    for (int i = 0; i < CH; i++) { int idx = base + i; if (idx < MN) s += g_cnt[idx]; }
    ssum[t] = s;
    __syncthreads();
    for (int off = 1; off < 1024; off <<= 1) {
        int v = (t >= off) ? ssum[t - off] : 0;
        __syncthreads();
        ssum[t] += v;
        __syncthreads();
    }
    int run = ssum[t] - s;
    for (int i = 0; i < CH; i++) {
        int idx = base + i;
        if (idx < MN) { int c = g_cnt[idx]; g_row[idx] = run; run += c; g_cnt[idx] = 0; }
    }
    if (t == 1023) g_row[MN] = ssum[1023];
}
__global__ void k_fill(const int* __restrict__ ei) {
    int e = blockIdx.x * blockDim.x + threadIdx.x;
    if (e < NE) {
        int src = ei[e];
        int dst = ei[NE + e];
        if (src >= 0 && src < MN && dst >= 0 && dst < MN) {
            int pos = atomicAdd(&g_cnt[dst], 1);
            g_srcs[g_row[dst] + pos] = src;
        }
    }
}

// ---------------- weight convert: W[K,N] fp32 -> hi/lo fp16 [N,K] -----------
__global__ void k_wcvt(const float* __restrict__ W, __half* __restrict__ hi,
                       __half* __restrict__ lo, int K, int N) {
    __shared__ float t[32][33];
    const int kb = blockIdx.y * 32, nb = blockIdx.x * 32;
    const int tx = threadIdx.x, ty0 = threadIdx.y;
#pragma unroll
    for (int i = 0; i < 4; i++) {
        int ty = ty0 + 8 * i;
        t[ty][tx] = W[(size_t)(kb + ty) * N + nb + tx];
    }
    __syncthreads();
#pragma unroll
    for (int i = 0; i < 4; i++) {
        int n = ty0 + 8 * i;
        float v = t[tx][n];
        __half h = __float2half_rn(v);
        hi[(size_t)(nb + n) * K + kb + tx] = h;
        lo[(size_t)(nb + n) * K + kb + tx] = __float2half_rn(v - __half2float(h));
    }
}

// ---------------- aggregation: (fp32|fp16 in) -> fp16 out, fp32 accum -------
__device__ __forceinline__ float4 load4(const float* p) {
    return *(const float4*)p;
}
__device__ __forceinline__ float4 load4(const __half* p) {
    uint2 u = __ldg((const uint2*)p);
    float2 a = __half22float2(*(__half2*)&u.x);
    float2 b = __half22float2(*(__half2*)&u.y);
    return make_float4(a.x, a.y, b.x, b.y);
}

template <int VEC, typename T>
__global__ void k_agg(const T* __restrict__ x, __half* __restrict__ oh) {
    const int node = (blockIdx.x * blockDim.x + threadIdx.x) >> 5;
    if (node >= MN) return;
    const int lane = threadIdx.x & 31;
    const int F = VEC * 128;

    float4 acc0[VEC], acc1[VEC];
#pragma unroll
    for (int v = 0; v < VEC; v++) {
        acc0[v] = load4(x + (size_t)node * F + (lane + 32 * v) * 4);
        acc1[v] = make_float4(0.f, 0.f, 0.f, 0.f);
    }

    const int s = g_row[node];
    const int e = g_row[node + 1];
    for (int i = s; i < e; i += 32) {
        const int my = (i + lane < e) ? g_srcs[i + lane] : 0;
        const int cnt = min(32, e - i);
        int t = 0;
        for (; t + 2 <= cnt; t += 2) {
            const int s0 = __shfl_sync(0xffffffff, my, t);
            const int s1 = __shfl_sync(0xffffffff, my, t + 1);
            const T* p0 = x + (size_t)s0 * F;
            const T* p1 = x + (size_t)s1 * F;
#pragma unroll
            for (int v = 0; v < VEC; v++) {
                float4 q0 = load4(p0 + (lane + 32 * v) * 4);
                float4 q1 = load4(p1 + (lane + 32 * v) * 4);
                acc0[v].x += q0.x; acc0[v].y += q0.y; acc0[v].z += q0.z; acc0[v].w += q0.w;
                acc1[v].x += q1.x; acc1[v].y += q1.y; acc1[v].z += q1.z; acc1[v].w += q1.w;
            }
        }
        if (t < cnt) {
            const int s0 = __shfl_sync(0xffffffff, my, t);
            const T* p0 = x + (size_t)s0 * F;
#pragma unroll
            for (int v = 0; v < VEC; v++) {
                float4 q0 = load4(p0 + (lane + 32 * v) * 4);
                acc0[v].x += q0.x; acc0[v].y += q0.y; acc0[v].z += q0.z; acc0[v].w += q0.w;
            }
        }
    }
#pragma unroll
    for (int v = 0; v < VEC; v++) {
        __half2 p0 = __floats2half2_rn(acc0[v].x + acc1[v].x, acc0[v].y + acc1[v].y);
        __half2 p1 = __floats2half2_rn(acc0[v].z + acc1[v].z, acc0[v].w + acc1[v].w);
        size_t off = (size_t)node * F + (lane + 32 * v) * 4;
        *(uint2*)(oh + off) = make_uint2(*(uint32_t*)&p0, *(uint32_t*)&p1);
    }
}

// ---------------- fused layer: C2 = act2(ReLU(A@W1+b1)@W2 + b2) --------------
// A [M,K1] fp16; W1 hi/lo [N1,K1]; W2 hi/lo [N2,N1]. Hidden kept in SMEM.
// EPI2: 0 = fp16 + ReLU (to act buffer), 1 = fp32 (final output)
#define PITCH 40                   // fp16 elems per smem row (80B, conflict-free)
#define TILE_B 10240               // one 128x32 fp16 array, 80B rows
#define PIPE_B (2 * 3 * TILE_B)    // 2 stages x (A, Bh, Bl)

// phase-1 loader: A tile + W1 hi/lo tile (stride K for all three)
__device__ __forceinline__ void load3(char* smbase, const __half* __restrict__ A,
                                      const __half* __restrict__ Bh,
                                      const __half* __restrict__ Bl,
                                      int tid, int m0, int K, int kb) {
    const uint32_t s0 = smem_u32(smbase);
#pragma unroll
    for (int i = 0; i < 2; i++) {
        const int idx = tid + 256 * i;
        const int r = idx >> 2, c4 = idx & 3;
        const uint32_t so = (uint32_t)(r * 80 + c4 * 16);
        const size_t aoff = (size_t)(m0 + r) * K + kb + c4 * 8;
        const size_t boff = (size_t)r * K + kb + c4 * 8;
        cp_async16(s0 + so,              A  + aoff);
        cp_async16(s0 + TILE_B + so,     Bh + boff);
        cp_async16(s0 + 2 * TILE_B + so, Bl + boff);
    }
}
// phase-2 loader: W2 hi/lo tile only
__device__ __forceinline__ void load2(char* smbase, const __half* __restrict__ Bh,
                                      const __half* __restrict__ Bl,
                                      int tid, int K, int kb) {
    const uint32_t s0 = smem_u32(smbase);
#pragma unroll
    for (int i = 0; i < 2; i++) {
        const int idx = tid + 256 * i;
        const int r = idx >> 2, c4 = idx & 3;
        const uint32_t so = (uint32_t)(r * 80 + c4 * 16);
        const size_t boff = (size_t)r * K + kb + c4 * 8;
        cp_async16(s0 + so,          Bh + boff);
        cp_async16(s0 + TILE_B + so, Bl + boff);
    }
}

__device__ __forceinline__ void compute_chunk(uint32_t sAU, uint32_t sBhU, uint32_t sBlU,
                                              uint32_t aOffB, uint32_t bOffB,
                                              float acc[2][8][4]) {
#pragma unroll
    for (int k16 = 0; k16 < 2; k16++) {
        const uint32_t kByte = (uint32_t)(k16 * 16 * 2);
        uint32_t a[2][4];
#pragma unroll
        for (int i = 0; i < 2; i++)
            ldsm_x4(a[i][0], a[i][1], a[i][2], a[i][3],
                    sAU + aOffB + kByte + (uint32_t)(i * 16 * PITCH * 2));
#pragma unroll
        for (int pass = 0; pass < 2; pass++) {
            const uint32_t bBase = ((pass == 0) ? sBhU : sBlU) + bOffB + kByte;
            uint32_t b2[8][2];
#pragma unroll
            for (int jj = 0; jj < 4; jj++)
                ldsm_x4(b2[2 * jj][0], b2[2 * jj][1], b2[2 * jj + 1][0], b2[2 * jj + 1][1],
                        bBase + (uint32_t)(jj * 16 * PITCH * 2));
#pragma unroll
            for (int i = 0; i < 2; i++)
#pragma unroll
                for (int j = 0; j < 8; j++) mma16816(acc[i][j], a[i], b2[j]);
        }
    }
}

template <int K1, int N1, int N2, int EPI2>
__global__ __launch_bounds__(256, 2)
void k_layer(const __half* __restrict__ A,
             const __half* __restrict__ W1h, const __half* __restrict__ W1l,
             const float* __restrict__ b1,
             const __half* __restrict__ W2h, const __half* __restrict__ W2l,
             const float* __restrict__ b2,
             float* __restrict__ outF, __half* __restrict__ outH, int M) {
    extern __shared__ char sm[];
    constexpr int HCH = N1 / 32;                       // H chunks (K of phase 2)
    constexpr int HOFF = PIPE_B;
    constexpr int B1OFF = HOFF + HCH * TILE_B;
    constexpr int B2OFF = B1OFF + N1 * 4;
    float* sb1 = (float*)(sm + B1OFF);
    float* sb2 = (float*)(sm + B2OFF);

    const int tid = threadIdx.x, warp = tid >> 5, lane = tid & 31;
    const int g = lane >> 2, tig = lane & 3;
    const int wm = warp >> 1, wn = warp & 1;           // 4x2 warp grid, 32x64 tile
    const int m0 = blockIdx.x * 128;

    if (tid < N1) sb1[tid] = b1[tid];
    if (tid < N2) sb2[tid] = b2[tid];

    const int aRow = wm * 32 + (lane & 15);
    const int aCol = (lane & 16) ? 8 : 0;
    const uint32_t aOffB = (uint32_t)(aRow * PITCH + aCol) * 2;
    const int bRow = wn * 64 + (lane & 7) + ((lane & 16) ? 8 : 0);
    const int bCol = (lane & 8) ? 8 : 0;
    const uint32_t bOffB = (uint32_t)(bRow * PITCH + bCol) * 2;

    const uint32_t smu = smem_u32(sm);
    const uint32_t Hu = smu + HOFF;
    float acc[2][8][4];

    // ---------------- phase 1: H = ReLU(A@W1 + b1) -> smem ----------------
    __syncthreads();   // biases visible
#pragma unroll
    for (int n1t = 0; n1t < N1 / 128; n1t++) {
#pragma unroll
        for (int i = 0; i < 2; i++)
#pragma unroll
            for (int j = 0; j < 8; j++)
#pragma unroll
                for (int r = 0; r < 4; r++) acc[i][j][r] = 0.f;

        const __half* W1hT = W1h + (size_t)n1t * 128 * K1;
        const __half* W1lT = W1l + (size_t)n1t * 128 * K1;
        constexpr int NKT = K1 / 32;
        load3(sm, A, W1hT, W1lT, tid, m0, K1, 0);
        cp_commit();
        for (int kt = 0; kt < NKT; kt++) {
            const int b = kt & 1;
            if (kt + 1 < NKT) {
                __syncthreads();
                load3(sm + (b ^ 1) * 3 * TILE_B, A, W1hT, W1lT, tid, m0, K1, (kt + 1) * 32);
                cp_commit();
                cp_wait<1>();
            } else {
                cp_wait<0>();
            }
            __syncthreads();
            const uint32_t sAU = smu + b * 3 * TILE_B;
            compute_chunk(sAU, sAU + TILE_B, sAU + 2 * TILE_B, aOffB, bOffB, acc);
        }
        // epilogue: ReLU + fp16 into H chunks (PITCH layout)
#pragma unroll
        for (int i = 0; i < 2; i++) {
#pragma unroll
            for (int hf = 0; hf < 2; hf++) {
                const int row = wm * 32 + i * 16 + g + hf * 8;
#pragma unroll
                for (int j = 0; j < 8; j++) {
                    const int col = wn * 64 + j * 8 + tig * 2;
                    float v0 = fmaxf(acc[i][j][2 * hf + 0] + sb1[n1t * 128 + col], 0.f);
                    float v1 = fmaxf(acc[i][j][2 * hf + 1] + sb1[n1t * 128 + col + 1], 0.f);
                    __half2 hp = __floats2half2_rn(v0, v1);
                    const uint32_t hoff = (uint32_t)((n1t * 4 + (col >> 5)) * TILE_B +
                                                     row * 80 + (col & 31) * 2);
                    *(uint32_t*)(sm + HOFF + hoff) = *(uint32_t*)&hp;
                }
            }
        }
        __syncthreads();   // H chunk complete; pipe buffers free
    }

    // ---------------- phase 2: C2 = H@W2 + b2 ----------------
#pragma unroll
    for (int n2t = 0; n2t < N2 / 128; n2t++) {
#pragma unroll
        for (int i = 0; i < 2; i++)
#pragma unroll
            for (int j = 0; j < 8; j++)
#pragma unroll
                for (int r = 0; r < 4; r++) acc[i][j][r] = 0.f;

        const __half* W2hT = W2h + (size_t)n2t * 128 * N1;
        const __half* W2lT = W2l + (size_t)n2t * 128 * N1;
        constexpr int NKT2 = N1 / 32;
        load2(sm, W2hT, W2lT, tid, N1, 0);
        cp_commit();
        for (int kt = 0; kt < NKT2; kt++) {
            const int b = kt & 1;
            if (kt + 1 < NKT2) {
                __syncthreads();
                load2(sm + (b ^ 1) * 2 * TILE_B, W2hT, W2lT, tid, N1, (kt + 1) * 32);
                cp_commit();
                cp_wait<1>();
            } else {
                cp_wait<0>();
            }
            __syncthreads();
            const uint32_t sBU = smu + b * 2 * TILE_B;
            compute_chunk(Hu + kt * TILE_B, sBU, sBU + TILE_B, aOffB, bOffB, acc);
        }
        // epilogue to global
#pragma unroll
        for (int i = 0; i < 2; i++) {
#pragma unroll
            for (int hf = 0; hf < 2; hf++) {
                const int row = m0 + wm * 32 + i * 16 + g + hf * 8;
                if (row >= M) continue;
#pragma unroll
                for (int j = 0; j < 8; j++) {
                    const int cl = wn * 64 + j * 8 + tig * 2;
                    float v0 = acc[i][j][2 * hf + 0] + sb2[n2t * 128 + cl];
                    float v1 = acc[i][j][2 * hf + 1] + sb2[n2t * 128 + cl + 1];
                    const size_t o = (size_t)row * N2 + n2t * 128 + cl;
                    if (EPI2 == 0) {
                        v0 = fmaxf(v0, 0.f);
                        v1 = fmaxf(v1, 0.f);
                        __half2 hp = __floats2half2_rn(v0, v1);
                        *(uint32_t*)(outH + o) = *(uint32_t*)&hp;
                    } else {
                        *(float2*)(outF + o) = make_float2(v0, v1);
                    }
                }
            }
        }
        __syncthreads();   // protect W2 stage reuse across n2t
    }
}

// ---------------- launch ----------------------------------------------------
extern "C" void kernel_launch(void* const* d_in, const int* in_sizes, int n_in,
                              void* d_out, int out_size) {
    const float* x  = (const float*)d_in[0];
    const int*   ei = (const int*)d_in[1];   // int32 (JAX x64 disabled)
    const float* W[6]  = {(const float*)d_in[2], (const float*)d_in[4], (const float*)d_in[6],
                          (const float*)d_in[8], (const float*)d_in[10], (const float*)d_in[12]};
    const float* Bv[6] = {(const float*)d_in[3], (const float*)d_in[5], (const float*)d_in[7],
                          (const float*)d_in[9], (const float*)d_in[11], (const float*)d_in[13]};
    const int WK[6] = {128, 128, 256, 256, 128, 128};
    const int WN[6] = {128, 256, 256, 128, 128, 128};
    float* out = (float*)d_out;

    __half *agg, *act, *wHi, *wLo;
    cudaGetSymbolAddress((void**)&agg, g_agg);
    cudaGetSymbolAddress((void**)&act, g_act);
    cudaGetSymbolAddress((void**)&wHi, g_wHi);
    cudaGetSymbolAddress((void**)&wLo, g_wLo);

    // smem sizes per layer template
    const int SM_L1 = PIPE_B + 4 * TILE_B + 128 * 4 + 256 * 4;   // 104448
    const int SM_L2 = PIPE_B + 8 * TILE_B + 256 * 4 + 128 * 4;   // 144896
    const int SM_L3 = PIPE_B + 4 * TILE_B + 128 * 4 + 128 * 4;   // 103936
    cudaFuncSetAttribute(k_layer<128, 128, 256, 0>, cudaFuncAttributeMaxDynamicSharedMemorySize, SM_L1);
    cudaFuncSetAttribute(k_layer<256, 256, 128, 0>, cudaFuncAttributeMaxDynamicSharedMemorySize, SM_L2);
    cudaFuncSetAttribute(k_layer<128, 128, 128, 1>, cudaFuncAttributeMaxDynamicSharedMemorySize, SM_L3);

    // --- CSR build ---
    k_zero_cnt<<<(MN + 255) / 256, 256>>>();
    k_count<<<(NE + 255) / 256, 256>>>(ei);
    k_scan<<<1, 1024>>>();
    k_fill<<<(NE + 255) / 256, 256>>>(ei);

    // --- weight conversion (tiled transpose + fp16 hi/lo split) ---
    for (int i = 0; i < 6; i++) {
        dim3 g(WN[i] / 32, WK[i] / 32), blk(32, 8);
        k_wcvt<<<g, blk>>>(W[i], wHi + (size_t)i * 65536, wLo + (size_t)i * 65536, WK[i], WN[i]);
    }

    const int AGG_BLOCKS = (MN * 32 + 255) / 256;
    const int GRID = MNP / 128;   // 392

    // --- layer 1 ---
    k_agg<1, float><<<AGG_BLOCKS, 256>>>(x, agg);
    k_layer<128, 128, 256, 0><<<GRID, 256, SM_L1>>>(
        agg, wHi + 0 * 65536, wLo + 0 * 65536, Bv[0],
        wHi + 1 * 65536, wLo + 1 * 65536, Bv[1], nullptr, act, MN);

    // --- layer 2 ---
    k_agg<2, __half><<<AGG_BLOCKS, 256>>>(act, agg);
    k_layer<256, 256, 128, 0><<<GRID, 256, SM_L2>>>(
        agg, wHi + 2 * 65536, wLo + 2 * 65536, Bv[2],
        wHi + 3 * 65536, wLo + 3 * 65536, Bv[3], nullptr, act, MN);

    // --- layer 3 ---
    k_agg<1, __half><<<AGG_BLOCKS, 256>>>(act, agg);
    k_layer<128, 128, 128, 1><<<GRID, 256, SM_L3>>>(
        agg, wHi + 4 * 65536, wLo + 4 * 65536, Bv[4],
        wHi + 5 * 65536, wLo + 5 * 65536, Bv[5], out, nullptr, MN);
}

// round 13
// speedup vs baseline: 1.2162x; 1.1702x over previous
#include <cuda_runtime.h>
#include <cuda_fp16.h>
#include <cstdint>

#define MN  50000
#define MNP 50176          // padded to 392*128 (unconditional GEMM tile loads)
#define NE  800000

// ---------------- scratch (device globals; no allocs allowed) ---------------
__device__ __half g_agg[(size_t)MNP * 256];     // aggregation out (layer A input)
__device__ __half g_act[(size_t)MNP * 256];     // layer output (next agg input)
__device__ __half g_wHi[6][65536];              // weights fp16 (transposed [N,K])
__device__ int g_row[MN + 1];
__device__ int g_cnt[MN];
__device__ int g_srcs[NE];

// ---------------- helpers ---------------------------------------------------
__device__ __forceinline__ uint32_t smem_u32(const void* p) {
    return (uint32_t)__cvta_generic_to_shared((void*)p);
}
__device__ __forceinline__ void cp_async16(uint32_t dst, const void* src) {
    asm volatile("cp.async.cg.shared.global [%0], [%1], 16;" :: "r"(dst), "l"(src));
}
__device__ __forceinline__ void cp_commit() {
    asm volatile("cp.async.commit_group;" ::: "memory");
}
template <int n>
__device__ __forceinline__ void cp_wait() {
    asm volatile("cp.async.wait_group %0;" :: "n"(n) : "memory");
}
__device__ __forceinline__ void ldsm_x4(uint32_t& r0, uint32_t& r1, uint32_t& r2,
                                        uint32_t& r3, uint32_t addr) {
    asm volatile("ldmatrix.sync.aligned.m8n8.x4.shared.b16 {%0,%1,%2,%3}, [%4];"
                 : "=r"(r0), "=r"(r1), "=r"(r2), "=r"(r3) : "r"(addr));
}
__device__ __forceinline__ void mma16816(float* d, const uint32_t* a, const uint32_t* b) {
    asm volatile("mma.sync.aligned.m16n8k16.row.col.f32.f16.f16.f32 "
                 "{%0,%1,%2,%3}, {%4,%5,%6,%7}, {%8,%9}, {%0,%1,%2,%3};"
                 : "+f"(d[0]), "+f"(d[1]), "+f"(d[2]), "+f"(d[3])
                 : "r"(a[0]), "r"(a[1]), "r"(a[2]), "r"(a[3]), "r"(b[0]), "r"(b[1]));
}

// ---------------- CSR build -------------------------------------------------
__global__ void k_zero_cnt() {
    int i = blockIdx.x * blockDim.x + threadIdx.x;
    if (i < MN) g_cnt[i] = 0;
}
__global__ void k_count(const int* __restrict__ ei) {
    int e = blockIdx.x * blockDim.x + threadIdx.x;
    if (e < NE) {
        int dst = ei[NE + e];
        if (dst >= 0 && dst < MN) atomicAdd(&g_cnt[dst], 1);
    }
}
__global__ void k_scan() {
    __shared__ int ssum[1024];
    const int t = threadIdx.x;
    const int CH = (MN + 1023) / 1024;
    const int base = t * CH;
    int s = 0;
    for (int i = 0; i < CH; i++) { int idx = base + i; if (idx < MN) s += g_cnt[idx]; }
    ssum[t] = s;
    __syncthreads();
    for (int off = 1; off < 1024; off <<= 1) {
        int v = (t >= off) ? ssum[t - off] : 0;
        __syncthreads();
        ssum[t] += v;
        __syncthreads();
    }
    int run = ssum[t] - s;
    for (int i = 0; i < CH; i++) {
        int idx = base + i;
        if (idx < MN) { int c = g_cnt[idx]; g_row[idx] = run; run += c; g_cnt[idx] = 0; }
    }
    if (t == 1023) g_row[MN] = ssum[1023];
}
__global__ void k_fill(const int* __restrict__ ei) {
    int e = blockIdx.x * blockDim.x + threadIdx.x;
    if (e < NE) {
        int src = ei[e];
        int dst = ei[NE + e];
        if (src >= 0 && src < MN && dst >= 0 && dst < MN) {
            int pos = atomicAdd(&g_cnt[dst], 1);
            g_srcs[g_row[dst] + pos] = src;
        }
    }
}

// ---------------- weight convert: W[K,N] fp32 -> fp16 [N,K] -----------------
__global__ void k_wcvt(const float* __restrict__ W, __half* __restrict__ hi, int K, int N) {
    __shared__ float t[32][33];
    const int kb = blockIdx.y * 32, nb = blockIdx.x * 32;
    const int tx = threadIdx.x, ty0 = threadIdx.y;
#pragma unroll
    for (int i = 0; i < 4; i++) {
        int ty = ty0 + 8 * i;
        t[ty][tx] = W[(size_t)(kb + ty) * N + nb + tx];
    }
    __syncthreads();
#pragma unroll
    for (int i = 0; i < 4; i++) {
        int n = ty0 + 8 * i;
        hi[(size_t)(nb + n) * K + kb + tx] = __float2half_rn(t[tx][n]);
    }
}

// ---------------- aggregation: (fp32|fp16 in) -> fp16 out, fp32 accum -------
__device__ __forceinline__ float4 load4(const float* p) {
    return *(const float4*)p;
}
__device__ __forceinline__ float4 load4(const __half* p) {
    uint2 u = __ldg((const uint2*)p);
    float2 a = __half22float2(*(__half2*)&u.x);
    float2 b = __half22float2(*(__half2*)&u.y);
    return make_float4(a.x, a.y, b.x, b.y);
}

template <int VEC, typename T>
__global__ void k_agg(const T* __restrict__ x, __half* __restrict__ oh) {
    const int node = (blockIdx.x * blockDim.x + threadIdx.x) >> 5;
    if (node >= MN) return;
    const int lane = threadIdx.x & 31;
    const int F = VEC * 128;

    float4 acc0[VEC], acc1[VEC];
#pragma unroll
    for (int v = 0; v < VEC; v++) {
        acc0[v] = load4(x + (size_t)node * F + (lane + 32 * v) * 4);
        acc1[v] = make_float4(0.f, 0.f, 0.f, 0.f);
    }

    const int s = g_row[node];
    const int e = g_row[node + 1];
    for (int i = s; i < e; i += 32) {
        const int my = (i + lane < e) ? g_srcs[i + lane] : 0;
        const int cnt = min(32, e - i);
        int t = 0;
        for (; t + 2 <= cnt; t += 2) {
            const int s0 = __shfl_sync(0xffffffff, my, t);
            const int s1 = __shfl_sync(0xffffffff, my, t + 1);
            const T* p0 = x + (size_t)s0 * F;
            const T* p1 = x + (size_t)s1 * F;
#pragma unroll
            for (int v = 0; v < VEC; v++) {
                float4 q0 = load4(p0 + (lane + 32 * v) * 4);
                float4 q1 = load4(p1 + (lane + 32 * v) * 4);
                acc0[v].x += q0.x; acc0[v].y += q0.y; acc0[v].z += q0.z; acc0[v].w += q0.w;
                acc1[v].x += q1.x; acc1[v].y += q1.y; acc1[v].z += q1.z; acc1[v].w += q1.w;
            }
        }
        if (t < cnt) {
            const int s0 = __shfl_sync(0xffffffff, my, t);
            const T* p0 = x + (size_t)s0 * F;
#pragma unroll
            for (int v = 0; v < VEC; v++) {
                float4 q0 = load4(p0 + (lane + 32 * v) * 4);
                acc0[v].x += q0.x; acc0[v].y += q0.y; acc0[v].z += q0.z; acc0[v].w += q0.w;
            }
        }
    }
#pragma unroll
    for (int v = 0; v < VEC; v++) {
        __half2 p0 = __floats2half2_rn(acc0[v].x + acc1[v].x, acc0[v].y + acc1[v].y);
        __half2 p1 = __floats2half2_rn(acc0[v].z + acc1[v].z, acc0[v].w + acc1[v].w);
        size_t off = (size_t)node * F + (lane + 32 * v) * 4;
        *(uint2*)(oh + off) = make_uint2(*(uint32_t*)&p0, *(uint32_t*)&p1);
    }
}

// ---------------- fused layer: C2 = act2(ReLU(A@W1+b1)@W2 + b2) --------------
// A [M,K1] fp16; W1 [N1,K1] fp16; W2 [N2,N1] fp16. Hidden kept in SMEM.
// EPI2: 0 = fp16 + ReLU (to act buffer), 1 = fp32 (final output)
#define PITCH 40                   // fp16 elems per smem row (80B, conflict-free)
#define TILE_B 10240               // one 128x32 fp16 array, 80B rows
#define PIPE_B (2 * 2 * TILE_B)    // 2 stages x (A, W)

// phase-1 loader: A tile + W1 tile
__device__ __forceinline__ void load_aw(char* smbase, const __half* __restrict__ A,
                                        const __half* __restrict__ Bh,
                                        int tid, int m0, int K, int kb) {
    const uint32_t s0 = smem_u32(smbase);
#pragma unroll
    for (int i = 0; i < 2; i++) {
        const int idx = tid + 256 * i;
        const int r = idx >> 2, c4 = idx & 3;
        const uint32_t so = (uint32_t)(r * 80 + c4 * 16);
        cp_async16(s0 + so,          A  + (size_t)(m0 + r) * K + kb + c4 * 8);
        cp_async16(s0 + TILE_B + so, Bh + (size_t)r * K + kb + c4 * 8);
    }
}
// phase-2 loader: W2 tile only
__device__ __forceinline__ void load_w(char* smbase, const __half* __restrict__ Bh,
                                       int tid, int K, int kb) {
    const uint32_t s0 = smem_u32(smbase);
#pragma unroll
    for (int i = 0; i < 2; i++) {
        const int idx = tid + 256 * i;
        const int r = idx >> 2, c4 = idx & 3;
        const uint32_t so = (uint32_t)(r * 80 + c4 * 16);
        cp_async16(s0 + so, Bh + (size_t)r * K + kb + c4 * 8);
    }
}

__device__ __forceinline__ void compute_chunk(uint32_t sAU, uint32_t sBU,
                                              uint32_t aOffB, uint32_t bOffB,
                                              float acc[2][8][4]) {
#pragma unroll
    for (int k16 = 0; k16 < 2; k16++) {
        const uint32_t kByte = (uint32_t)(k16 * 16 * 2);
        uint32_t a[2][4];
#pragma unroll
        for (int i = 0; i < 2; i++)
            ldsm_x4(a[i][0], a[i][1], a[i][2], a[i][3],
                    sAU + aOffB + kByte + (uint32_t)(i * 16 * PITCH * 2));
        uint32_t b2[8][2];
#pragma unroll
        for (int jj = 0; jj < 4; jj++)
            ldsm_x4(b2[2 * jj][0], b2[2 * jj][1], b2[2 * jj + 1][0], b2[2 * jj + 1][1],
                    sBU + bOffB + kByte + (uint32_t)(jj * 16 * PITCH * 2));
#pragma unroll
        for (int i = 0; i < 2; i++)
#pragma unroll
            for (int j = 0; j < 8; j++) mma16816(acc[i][j], a[i], b2[j]);
    }
}

template <int K1, int N1, int N2, int EPI2>
__global__ __launch_bounds__(256, 2)
void k_layer(const __half* __restrict__ A,
             const __half* __restrict__ W1h, const float* __restrict__ b1,
             const __half* __restrict__ W2h, const float* __restrict__ b2,
             float* __restrict__ outF, __half* __restrict__ outH, int M) {
    extern __shared__ char sm[];
    constexpr int HCH = N1 / 32;                       // H chunks (K of phase 2)
    constexpr int HOFF = PIPE_B;
    constexpr int B1OFF = HOFF + HCH * TILE_B;
    constexpr int B2OFF = B1OFF + N1 * 4;
    float* sb1 = (float*)(sm + B1OFF);
    float* sb2 = (float*)(sm + B2OFF);

    const int tid = threadIdx.x, warp = tid >> 5, lane = tid & 31;
    const int g = lane >> 2, tig = lane & 3;
    const int wm = warp >> 1, wn = warp & 1;           // 4x2 warp grid, 32x64 tile
    const int m0 = blockIdx.x * 128;

    if (tid < N1) sb1[tid] = b1[tid];
    if (tid < N2) sb2[tid] = b2[tid];

    const int aRow = wm * 32 + (lane & 15);
    const int aCol = (lane & 16) ? 8 : 0;
    const uint32_t aOffB = (uint32_t)(aRow * PITCH + aCol) * 2;
    const int bRow = wn * 64 + (lane & 7) + ((lane & 16) ? 8 : 0);
    const int bCol = (lane & 8) ? 8 : 0;
    const uint32_t bOffB = (uint32_t)(bRow * PITCH + bCol) * 2;

    const uint32_t smu = smem_u32(sm);
    const uint32_t Hu = smu + HOFF;
    float acc[2][8][4];

    // ---------------- phase 1: H = ReLU(A@W1 + b1) -> smem ----------------
    __syncthreads();   // biases visible
#pragma unroll
    for (int n1t = 0; n1t < N1 / 128; n1t++) {
#pragma unroll
        for (int i = 0; i < 2; i++)
#pragma unroll
            for (int j = 0; j < 8; j++)
#pragma unroll
                for (int r = 0; r < 4; r++) acc[i][j][r] = 0.f;

        const __half* W1T = W1h + (size_t)n1t * 128 * K1;
        constexpr int NKT = K1 / 32;
        load_aw(sm, A, W1T, tid, m0, K1, 0);
        cp_commit();
        for (int kt = 0; kt < NKT; kt++) {
            const int b = kt & 1;
            if (kt + 1 < NKT) {
                __syncthreads();
                load_aw(sm + (b ^ 1) * 2 * TILE_B, A, W1T, tid, m0, K1, (kt + 1) * 32);
                cp_commit();
                cp_wait<1>();
            } else {
                cp_wait<0>();
            }
            __syncthreads();
            const uint32_t sAU = smu + b * 2 * TILE_B;
            compute_chunk(sAU, sAU + TILE_B, aOffB, bOffB, acc);
        }
        // epilogue: ReLU + fp16 into H chunks (PITCH layout)
#pragma unroll
        for (int i = 0; i < 2; i++) {
#pragma unroll
            for (int hf = 0; hf < 2; hf++) {
                const int row = wm * 32 + i * 16 + g + hf * 8;
#pragma unroll
                for (int j = 0; j < 8; j++) {
                    const int col = wn * 64 + j * 8 + tig * 2;
                    float v0 = fmaxf(acc[i][j][2 * hf + 0] + sb1[n1t * 128 + col], 0.f);
                    float v1 = fmaxf(acc[i][j][2 * hf + 1] + sb1[n1t * 128 + col + 1], 0.f);
                    __half2 hp = __floats2half2_rn(v0, v1);
                    const uint32_t hoff = (uint32_t)((n1t * 4 + (col >> 5)) * TILE_B +
                                                     row * 80 + (col & 31) * 2);
                    *(uint32_t*)(sm + HOFF + hoff) = *(uint32_t*)&hp;
                }
            }
        }
        __syncthreads();   // H chunk complete; pipe buffers free
    }

    // ---------------- phase 2: C2 = H@W2 + b2 ----------------
#pragma unroll
    for (int n2t = 0; n2t < N2 / 128; n2t++) {
#pragma unroll
        for (int i = 0; i < 2; i++)
#pragma unroll
            for (int j = 0; j < 8; j++)
#pragma unroll
                for (int r = 0; r < 4; r++) acc[i][j][r] = 0.f;

        const __half* W2T = W2h + (size_t)n2t * 128 * N1;
        constexpr int NKT2 = N1 / 32;
        load_w(sm, W2T, tid, N1, 0);
        cp_commit();
        for (int kt = 0; kt < NKT2; kt++) {
            const int b = kt & 1;
            if (kt + 1 < NKT2) {
                __syncthreads();
                load_w(sm + (b ^ 1) * TILE_B, W2T, tid, N1, (kt + 1) * 32);
                cp_commit();
                cp_wait<1>();
            } else {
                cp_wait<0>();
            }
            __syncthreads();
            compute_chunk(Hu + kt * TILE_B, smu + b * TILE_B, aOffB, bOffB, acc);
        }
        // epilogue to global
#pragma unroll
        for (int i = 0; i < 2; i++) {
#pragma unroll
            for (int hf = 0; hf < 2; hf++) {
                const int row = m0 + wm * 32 + i * 16 + g + hf * 8;
                if (row >= M) continue;
#pragma unroll
                for (int j = 0; j < 8; j++) {
                    const int cl = wn * 64 + j * 8 + tig * 2;
                    float v0 = acc[i][j][2 * hf + 0] + sb2[n2t * 128 + cl];
                    float v1 = acc[i][j][2 * hf + 1] + sb2[n2t * 128 + cl + 1];
                    const size_t o = (size_t)row * N2 + n2t * 128 + cl;
                    if (EPI2 == 0) {
                        v0 = fmaxf(v0, 0.f);
                        v1 = fmaxf(v1, 0.f);
                        __half2 hp = __floats2half2_rn(v0, v1);
                        *(uint32_t*)(outH + o) = *(uint32_t*)&hp;
                    } else {
                        *(float2*)(outF + o) = make_float2(v0, v1);
                    }
                }
            }
        }
        __syncthreads();   // protect W2 stage reuse across n2t
    }
}

// ---------------- launch ----------------------------------------------------
extern "C" void kernel_launch(void* const* d_in, const int* in_sizes, int n_in,
                              void* d_out, int out_size) {
    const float* x  = (const float*)d_in[0];
    const int*   ei = (const int*)d_in[1];   // int32 (JAX x64 disabled)
    const float* W[6]  = {(const float*)d_in[2], (const float*)d_in[4], (const float*)d_in[6],
                          (const float*)d_in[8], (const float*)d_in[10], (const float*)d_in[12]};
    const float* Bv[6] = {(const float*)d_in[3], (const float*)d_in[5], (const float*)d_in[7],
                          (const float*)d_in[9], (const float*)d_in[11], (const float*)d_in[13]};
    const int WK[6] = {128, 128, 256, 256, 128, 128};
    const int WN[6] = {128, 256, 256, 128, 128, 128};
    float* out = (float*)d_out;

    __half *agg, *act, *wHi;
    cudaGetSymbolAddress((void**)&agg, g_agg);
    cudaGetSymbolAddress((void**)&act, g_act);
    cudaGetSymbolAddress((void**)&wHi, g_wHi);

    // smem sizes per layer template
    const int SM_L1 = PIPE_B + 4 * TILE_B + 128 * 4 + 256 * 4;   // 83456
    const int SM_L2 = PIPE_B + 8 * TILE_B + 256 * 4 + 128 * 4;   // 124416
    const int SM_L3 = PIPE_B + 4 * TILE_B + 128 * 4 + 128 * 4;   // 82944
    cudaFuncSetAttribute(k_layer<128, 128, 256, 0>, cudaFuncAttributeMaxDynamicSharedMemorySize, SM_L1);
    cudaFuncSetAttribute(k_layer<256, 256, 128, 0>, cudaFuncAttributeMaxDynamicSharedMemorySize, SM_L2);
    cudaFuncSetAttribute(k_layer<128, 128, 128, 1>, cudaFuncAttributeMaxDynamicSharedMemorySize, SM_L3);

    // --- CSR build ---
    k_zero_cnt<<<(MN + 255) / 256, 256>>>();
    k_count<<<(NE + 255) / 256, 256>>>(ei);
    k_scan<<<1, 1024>>>();
    k_fill<<<(NE + 255) / 256, 256>>>(ei);

    // --- weight conversion (tiled transpose + fp16) ---
    for (int i = 0; i < 6; i++) {
        dim3 g(WN[i] / 32, WK[i] / 32), blk(32, 8);
        k_wcvt<<<g, blk>>>(W[i], wHi + (size_t)i * 65536, WK[i], WN[i]);
    }

    const int AGG_BLOCKS = (MN * 32 + 255) / 256;
    const int GRID = MNP / 128;   // 392

    // --- layer 1 ---
    k_agg<1, float><<<AGG_BLOCKS, 256>>>(x, agg);
    k_layer<128, 128, 256, 0><<<GRID, 256, SM_L1>>>(
        agg, wHi + 0 * 65536, Bv[0], wHi + 1 * 65536, Bv[1], nullptr, act, MN);

    // --- layer 2 ---
    k_agg<2, __half><<<AGG_BLOCKS, 256>>>(act, agg);
    k_layer<256, 256, 128, 0><<<GRID, 256, SM_L2>>>(
        agg, wHi + 2 * 65536, Bv[2], wHi + 3 * 65536, Bv[3], nullptr, act, MN);

    // --- layer 3 ---
    k_agg<1, __half><<<AGG_BLOCKS, 256>>>(act, agg);
    k_layer<128, 128, 128, 1><<<GRID, 256, SM_L3>>>(
        agg, wHi + 4 * 65536, Bv[4], wHi + 5 * 65536, Bv[5], out, nullptr, MN);
}